// round 7
// baseline (speedup 1.0000x reference)
#include <cuda_runtime.h>
#include <cuda_bf16.h>
#include <cstdint>

#define TT   512
#define BB   128
#define NIN  256
#define NH   1024
#define NOUT 32
#define MM   (TT * BB)

// ---------------- device scratch ----------------
__device__ __nv_bfloat16 g_spkb[MM * NIN];          // spikes as bf16 (32 MB)
__device__ __nv_bfloat16 g_wsplit[3 * NH * NIN];    // 3-way bf16 split of w_h
__device__ unsigned int  g_zbits[MM * 32];          // hidden spike bitmask (natural layout)

// ---------------- prep: spikes fp32 -> bf16 (exact: values 0/1) ----------------
__global__ void cvt_spk_kernel(const float* __restrict__ sp) {
    size_t i = (size_t)blockIdx.x * blockDim.x + threadIdx.x;
    float4 f = ((const float4*)sp)[i];
    __nv_bfloat162 lo = {__float2bfloat16_rn(f.x), __float2bfloat16_rn(f.y)};
    __nv_bfloat162 hi = {__float2bfloat16_rn(f.z), __float2bfloat16_rn(f.w)};
    ((__nv_bfloat162*)g_spkb)[i * 2]     = lo;
    ((__nv_bfloat162*)g_spkb)[i * 2 + 1] = hi;
}

// ---------------- prep: 3-way bf16 split of w_h (w = b0+b1+b2 exactly to 2^-26) ----------------
__global__ void wsplit_kernel(const float* __restrict__ w) {
    int k = blockIdx.x * blockDim.x + threadIdx.x;
    if (k < NH * NIN) {
        float x = w[k];
        __nv_bfloat16 b0 = __float2bfloat16_rn(x);
        float r1 = x - __bfloat162float(b0);
        __nv_bfloat16 b1 = __float2bfloat16_rn(r1);
        float r2 = r1 - __bfloat162float(b1);
        __nv_bfloat16 b2 = __float2bfloat16_rn(r2);
        g_wsplit[k]                = b0;
        g_wsplit[NH * NIN + k]     = b1;
        g_wsplit[2 * NH * NIN + k] = b2;
    }
}

// ---------------- PTX helpers (baseline PTX: sm_75/80 features, compile for sm_103) -------
__device__ __forceinline__ uint32_t smem_u32(const void* p) {
    uint32_t a;
    asm("{ .reg .u64 t; cvta.to.shared.u64 t, %1; cvt.u32.u64 %0, t; }" : "=r"(a) : "l"(p));
    return a;
}
__device__ __forceinline__ void ldsm_x4(uint32_t* d, uint32_t addr) {
    asm volatile("ldmatrix.sync.aligned.m8n8.x4.shared.b16 {%0,%1,%2,%3}, [%4];"
                 : "=r"(d[0]), "=r"(d[1]), "=r"(d[2]), "=r"(d[3]) : "r"(addr));
}
__device__ __forceinline__ void mma_bf16(float* c, const uint32_t* a, uint32_t b0, uint32_t b1) {
    asm volatile(
        "mma.sync.aligned.m16n8k16.row.col.f32.bf16.bf16.f32 "
        "{%0,%1,%2,%3}, {%4,%5,%6,%7}, {%8,%9}, {%0,%1,%2,%3};"
        : "+f"(c[0]), "+f"(c[1]), "+f"(c[2]), "+f"(c[3])
        : "r"(a[0]), "r"(a[1]), "r"(a[2]), "r"(a[3]), "r"(b0), "r"(b1));
}

// ---------------- fused GEMM (mma.sync bf16) + CUBA LIF scan ----------------
// Grid (16, 128): bx = 64-h tile, by = batch. Block 256 = 8 warps.
// Per CTA: 4 t-chunks of 128; chunk-GEMM [128 x 64 x 768] -> stage -> scan.
// smem rows padded to 264 bf16 (528 B) -> conflict-free ldmatrix.
#define PADK   264
#define SM_A   0                          // [128][264] bf16 = 67584
#define SM_B   67584                      // [3][64][264] bf16 = 101376
#define SM_ST  168960                     // stage [128][65] f32 = 33280
#define F_SMEM 202240

__global__ __launch_bounds__(256) void snn_kernel() {
    extern __shared__ char sm[];
    uint32_t sbase = smem_u32(sm);
    float* stage = (float*)(sm + SM_ST);
    int tid = threadIdx.x;
    int wid = tid >> 5, lane = tid & 31;
    int ht = blockIdx.x;           // h-tile (64 h)
    int b  = blockIdx.y;
    int n0g = ht << 6;

    // ---- load B: 3 splits x [64][256] bf16, padded rows ----
    for (int idx = tid; idx < 3 * 64 * 32; idx += 256) {
        int s = idx >> 11, rem = idx & 2047;
        int n = rem >> 5, k16 = rem & 31;
        uint4 v = *(const uint4*)(g_wsplit + (size_t)s * NH * NIN + (size_t)(n0g + n) * NIN + k16 * 8);
        *(uint4*)(sm + SM_B + ((s * 64 + n) * PADK + k16 * 8) * 2) = v;
    }
    // ---- load A chunk 0 ----
    for (int idx = tid; idx < 128 * 32; idx += 256) {
        int r = idx >> 5, k16 = idx & 31;
        uint4 v = *(const uint4*)(g_spkb + ((size_t)r * BB + b) * NIN + k16 * 8);
        *(uint4*)(sm + SM_A + (r * PADK + k16 * 8) * 2) = v;
    }
    __syncthreads();

    // warp tiling: 4 m-warps x 2 n-warps
    int wm = wid & 3, wn = wid >> 2;
    int m_base = wm << 5;          // 32 t-rows
    int n_base = wn << 5;          // 32 h-cols

    // ldmatrix lane addressing
    int g = lane >> 3, wln = lane & 7;
    int a_row = m_base + wln + ((g & 1) << 3);
    int a_col = (g >> 1) << 3;
    uint32_t aAddr = sbase + SM_A + (a_row * PADK + a_col) * 2;
    int b_row = n_base + wln + ((g & 2) << 2);        // +8 for g>=2
    int b_col = (g & 1) << 3;
    uint32_t bAddr = sbase + SM_B + (b_row * PADK + b_col) * 2;

    // LIF state (scan warps 0-1; lanes own h = tid within [0,64))
    float v_m = 0.f, i_s = 0.f;

    for (int chunk = 0; chunk < 4; chunk++) {
        float acc[2][4][4];
#pragma unroll
        for (int i = 0; i < 2; i++)
#pragma unroll
            for (int j = 0; j < 4; j++)
#pragma unroll
                for (int q = 0; q < 4; q++) acc[i][j][q] = 0.f;

        // ---- chunk GEMM: K = 3 splits x 256 ----
#pragma unroll
        for (int s = 0; s < 3; s++) {
            uint32_t bA = bAddr + s * 64 * PADK * 2;
#pragma unroll
            for (int ks = 0; ks < 16; ks++) {
                uint32_t a0[4], a1[4], bb0[4], bb1[4];
                ldsm_x4(a0, aAddr + ks * 32);
                ldsm_x4(a1, aAddr + ks * 32 + 16 * PADK * 2);
                ldsm_x4(bb0, bA + ks * 32);                      // n-tiles 0,1
                ldsm_x4(bb1, bA + ks * 32 + 16 * PADK * 2);      // n-tiles 2,3
                mma_bf16(acc[0][0], a0, bb0[0], bb0[1]);
                mma_bf16(acc[0][1], a0, bb0[2], bb0[3]);
                mma_bf16(acc[0][2], a0, bb1[0], bb1[1]);
                mma_bf16(acc[0][3], a0, bb1[2], bb1[3]);
                mma_bf16(acc[1][0], a1, bb0[0], bb0[1]);
                mma_bf16(acc[1][1], a1, bb0[2], bb0[3]);
                mma_bf16(acc[1][2], a1, bb1[0], bb1[1]);
                mma_bf16(acc[1][3], a1, bb1[2], bb1[3]);
            }
        }
        __syncthreads();   // prev scan done (stage free), all sA reads done

        // ---- accumulators -> stage [t][h], pad 65 ----
        int r0 = m_base + (lane >> 2);
        int cc = n_base + ((lane & 3) << 1);
#pragma unroll
        for (int i = 0; i < 2; i++) {
#pragma unroll
            for (int j = 0; j < 4; j++) {
                int rr = r0 + i * 16;
                int c2 = cc + j * 8;
                stage[rr * 65 + c2]           = acc[i][j][0];
                stage[rr * 65 + c2 + 1]       = acc[i][j][1];
                stage[(rr + 8) * 65 + c2]     = acc[i][j][2];
                stage[(rr + 8) * 65 + c2 + 1] = acc[i][j][3];
            }
        }
        __syncthreads();

        // ---- warps 0-1: LIF scan over 128 steps; warps 2-7: prefetch next A ----
        if (wid < 2) {
            int h = tid;   // 0..63
            int zoff = (ht << 1) + wid;
#pragma unroll 4
            for (int ts = 0; ts < 128; ts++) {
                float c = stage[ts * 65 + h];
                i_s = i_s * 0.875f + c;
                v_m = v_m + 0.125f * (i_s - v_m);
                bool z = (v_m - 1.0f) > 0.0f;
                if (z) v_m = 0.f;
                unsigned m = __ballot_sync(0xffffffffu, z);
                if (lane == 0)
                    g_zbits[((size_t)(chunk * 128 + ts) * BB + b) * 32 + zoff] = m;
            }
        } else if (chunk + 1 < 4) {
            int t0 = (chunk + 1) * 128;
            for (int idx = tid - 64; idx < 128 * 32; idx += 192) {
                int r = idx >> 5, k16 = idx & 31;
                uint4 v = *(const uint4*)(g_spkb + ((size_t)(t0 + r) * BB + b) * NIN + k16 * 8);
                *(uint4*)(sm + SM_A + (r * PADK + k16 * 8) * 2) = v;
            }
        }
        __syncthreads();
    }
}

// ---------------- output currents + fused LI scan (R5 version, known-good) ----------------
#define COUT_SMEM (NH * 33 * 4 + TT * NOUT * 4)

__global__ __launch_bounds__(1024, 1) void cout_li_kernel(const float* __restrict__ w_o,
                                                          float* __restrict__ out) {
    extern __shared__ float smem[];
    float* s_wT = smem;
    float* s_c  = smem + NH * 33;
    int tid = threadIdx.x;

    for (int k = tid; k < NOUT * NH; k += 1024) {
        int o = k >> 10;
        int h = k & 1023;
        s_wT[h * 33 + o] = w_o[k];
    }
    __syncthreads();

    int b = blockIdx.x;
    int warp = tid >> 5, lane = tid & 31;

    for (int t = warp; t < TT; t += 32) {
        unsigned m = g_zbits[((size_t)t * BB + b) * 32 + lane];
        float c0 = 0.f, c1 = 0.f;
#pragma unroll
        for (int wi = 0; wi < 32; wi++) {
            unsigned mw = __shfl_sync(0xffffffffu, m, wi);
            int base = wi * (32 * 33) + lane;
            while (mw) {
                int p = __ffs(mw) - 1; mw &= mw - 1;
                c0 += s_wT[base + p * 33];
                if (mw) {
                    int p2 = __ffs(mw) - 1; mw &= mw - 1;
                    c1 += s_wT[base + p2 * 33];
                }
            }
        }
        s_c[t * 32 + lane] = c0 + c1;
    }
    __syncthreads();

    if (warp == 0) {
        float v = 0.f, cur = 0.f;
        float cb[4];
#pragma unroll
        for (int j = 0; j < 4; j++) cb[j] = s_c[j * 32 + lane];
        for (int t0 = 0; t0 < TT; t0 += 4) {
            float cn[4];
            if (t0 + 4 < TT) {
#pragma unroll
                for (int j = 0; j < 4; j++) cn[j] = s_c[(t0 + 4 + j) * 32 + lane];
            }
#pragma unroll
            for (int j = 0; j < 4; j++) {
                cur = cur * 0.875f + cb[j];
                v = v + 0.125f * (cur - v);
                out[((size_t)(t0 + j) * BB + b) * 32 + lane] = v;
            }
#pragma unroll
            for (int j = 0; j < 4; j++) cb[j] = cn[j];
        }
    }
}

// ---------------- launch ----------------
extern "C" void kernel_launch(void* const* d_in, const int* in_sizes, int n_in,
                              void* d_out, int out_size) {
    const float* spikes = (const float*)d_in[0];   // [512,128,256]
    const float* w_h    = (const float*)d_in[1];   // [1024,256]
    const float* w_o    = (const float*)d_in[2];   // [32,1024]
    float* out = (float*)d_out;                    // [512,128,32]

    cudaFuncSetAttribute(snn_kernel,     cudaFuncAttributeMaxDynamicSharedMemorySize, F_SMEM);
    cudaFuncSetAttribute(cout_li_kernel, cudaFuncAttributeMaxDynamicSharedMemorySize, COUT_SMEM);

    cvt_spk_kernel<<<MM * NIN / 4 / 256, 256>>>(spikes);
    wsplit_kernel<<<(NH * NIN + 255) / 256, 256>>>(w_h);
    snn_kernel<<<dim3(NH / 64, BB), 256, F_SMEM>>>();
    cout_li_kernel<<<BB, 1024, COUT_SMEM>>>(w_o, out);
}

// round 8
// speedup vs baseline: 1.1820x; 1.1820x over previous
#include <cuda_runtime.h>
#include <cstdint>

#define TT   512
#define BB   128
#define NIN  256
#define NH   1024
#define NOUT 32
#define MM   (TT * BB)

// ---------------- device scratch ----------------
__device__ unsigned int g_idx[TT * BB * 64];      // per (t,b): up to 256 uint8 indices
__device__ int          g_cnt[TT * BB];
__device__ unsigned int g_zbits[MM * 32];         // word w bit p <-> h = w*32+p
__device__ float        g_whT[NIN * NH];          // w_h transposed [i][h]
__device__ float        g_cop[2 * (size_t)MM * NOUT];  // per-h-half partial output currents

// ---------------- transpose w_h [H][I] -> [I][H] ----------------
__global__ void transpose_wh_kernel(const float* __restrict__ w_h) {
    int k = blockIdx.x * blockDim.x + threadIdx.x;
    if (k < NH * NIN) {
        int h = k >> 8;
        int i = k & 255;
        g_whT[i * NH + h] = w_h[k];
    }
}

// ---------------- compact: warp per (t,b) ----------------
__global__ __launch_bounds__(256) void compact_kernel(const float* __restrict__ spikes) {
    int gw   = (blockIdx.x * blockDim.x + threadIdx.x) >> 5;
    int lane = threadIdx.x & 31;
    const int NW = 8192;

    for (int u = gw; u < TT * BB; u += NW) {
        const float4* p = (const float4*)(spikes + (size_t)u * NIN) + lane * 2;
        float4 a = __ldcs(p);
        float4 b = __ldcs(p + 1);
        unsigned m8 = 0;
        m8 |= (a.x != 0.f) ? 1u   : 0u;
        m8 |= (a.y != 0.f) ? 2u   : 0u;
        m8 |= (a.z != 0.f) ? 4u   : 0u;
        m8 |= (a.w != 0.f) ? 8u   : 0u;
        m8 |= (b.x != 0.f) ? 16u  : 0u;
        m8 |= (b.y != 0.f) ? 32u  : 0u;
        m8 |= (b.z != 0.f) ? 64u  : 0u;
        m8 |= (b.w != 0.f) ? 128u : 0u;

        int c  = __popc(m8);
        int sc = c;
#pragma unroll
        for (int off = 1; off < 32; off <<= 1) {
            int n = __shfl_up_sync(0xffffffffu, sc, off);
            if (lane >= off) sc += n;
        }
        int tot = __shfl_sync(0xffffffffu, sc, 31);
        int ex  = sc - c;

        unsigned char* outp = (unsigned char*)g_idx + (size_t)u * 256 + ex;
        int base_i = lane << 3;
        unsigned mm = m8;
        int k = 0;
        while (mm) {
            int j = __ffs(mm) - 1; mm &= mm - 1;
            outp[k++] = (unsigned char)(base_i + j);
        }
        if (lane == 31) g_cnt[u] = tot;
    }
}

// ---------------- fused sparse projection + CUBA LIF scan ----------------
// Grid (8,16): bx = 128-h tile, by = 8-batch group. Block 512 = 16 warps.
// Warp = (batch, h-half); lane owns h-pair (h0+hh*64+lane, +32) via LDS.64.
// 4 warps/SMSP (vs 2 in R5) -> double latency hiding at same crossbar bytes.
// Per-h accumulation order identical to R5 -> identical spikes.
#define LIF_SMEM (NIN * 128 * 4)

__global__ __launch_bounds__(512) void lif_kernel() {
    extern __shared__ float2 s_w2[];   // [i*64 + hh*32 + l] = (w[i][h0+hh*64+l], w[i][h0+hh*64+32+l])
    int tid = threadIdx.x;
    int h0  = blockIdx.x << 7;
    int b0  = blockIdx.y << 3;

    for (int k = tid; k < NIN * 64; k += 512) {
        int i = k >> 6, m = k & 63;
        int hh = m >> 5, l5 = m & 31;
        const float* src = g_whT + i * NH + h0 + (hh << 6) + l5;
        s_w2[k] = make_float2(src[0], src[32]);
    }
    __syncthreads();   // only barrier

    int lane = tid & 31;
    int w    = tid >> 5;
    int bl   = w >> 1, hh = w & 1;
    int b    = b0 + bl;
    const float2* wrow = s_w2 + (hh << 5) + lane;
    int wb   = (blockIdx.x << 2) + (hh << 1);   // zbits word base

    size_t tb = (size_t)b;
    uint4 p0 = ((const uint4*)(g_idx + tb * 64))[0];
    uint4 p1 = ((const uint4*)(g_idx + tb * 64))[1];
    int cnt_n = g_cnt[tb];

    float v0 = 0.f, v1 = 0.f, i0 = 0.f, i1 = 0.f;

    for (int t = 0; t < TT; t++) {
        uint4 q0 = p0, q1 = p1;
        int cnt = cnt_n;
        size_t tbn = tb + BB;
        if (t + 1 < TT) {
            p0 = ((const uint4*)(g_idx + tbn * 64))[0];
            p1 = ((const uint4*)(g_idx + tbn * 64))[1];
            cnt_n = g_cnt[tbn];
        }

        unsigned w8[8] = {q0.x, q0.y, q0.z, q0.w, q1.x, q1.y, q1.z, q1.w};
        int nw = cnt >> 2;

        float c0 = 0.f, c1 = 0.f;   // per-h chains, exact index order
#pragma unroll
        for (int kw = 0; kw < 8; kw++) {
            if (kw >= nw) break;
            unsigned wd = w8[kw];
#pragma unroll
            for (int s = 0; s < 4; s++) {
                float2 f = wrow[((wd >> (8 * s)) & 255u) << 6];
                c0 += f.x; c1 += f.y;
            }
        }
        for (int kw = 8; kw < nw; kw++) {   // rare (>32 actives)
            unsigned wd = g_idx[tb * 64 + kw];
#pragma unroll
            for (int s = 0; s < 4; s++) {
                float2 f = wrow[((wd >> (8 * s)) & 255u) << 6];
                c0 += f.x; c1 += f.y;
            }
        }
        int rem = cnt & 3;
        if (rem) {
            unsigned wd;
            if (nw >= 8) {
                wd = g_idx[tb * 64 + nw];
            } else {
                wd = w8[0];
#pragma unroll
                for (int k = 1; k < 8; k++) if (nw == k) wd = w8[k];
            }
#pragma unroll
            for (int s = 0; s < 3; s++) {
                if (s < rem) {
                    float2 f = wrow[((wd >> (8 * s)) & 255u) << 6];
                    c0 += f.x; c1 += f.y;
                }
            }
        }

        // CUBA LIF (exact fp32, mirrors reference)
        i0 = i0 * 0.875f + c0;  v0 = v0 + 0.125f * (i0 - v0);
        i1 = i1 * 0.875f + c1;  v1 = v1 + 0.125f * (i1 - v1);
        bool z0 = (v0 - 1.0f) > 0.0f; if (z0) v0 = 0.f;
        bool z1 = (v1 - 1.0f) > 0.0f; if (z1) v1 = 0.f;

        unsigned m0 = __ballot_sync(0xffffffffu, z0);   // word wb   (h0+hh*64 .. +31)
        unsigned m1 = __ballot_sync(0xffffffffu, z1);   // word wb+1 (+32 .. +63)
        if (lane == 0)
            *(unsigned long long*)(g_zbits + tb * 32 + wb) =
                (unsigned long long)m0 | ((unsigned long long)m1 << 32);

        tb = tbn;
    }
}

// ---------------- output partial currents: h-half per block (3 CTAs/SM) ----------------
#define COUT_SMEM (512 * 33 * 4)

__global__ __launch_bounds__(512) void cout_kernel(const float* __restrict__ w_o) {
    extern __shared__ float s_wT[];   // [hl*33 + o], hl in [0,512)
    int bid = blockIdx.x;             // 0..255
    int b = bid >> 1, hh = bid & 1;
    int tid = threadIdx.x;

    for (int k = tid; k < NOUT * 512; k += 512) {
        int o = k >> 9, hl = k & 511;
        s_wT[hl * 33 + o] = w_o[o * NH + (hh << 9) + hl];
    }
    __syncthreads();

    int warp = tid >> 5, lane = tid & 31;
    float* dst = g_cop + (size_t)hh * MM * NOUT;

    for (int t = warp; t < TT; t += 16) {
        size_t tb = (size_t)t * BB + b;
        unsigned m = 0;
        if (lane < 16) m = g_zbits[tb * 32 + (hh << 4) + lane];
        float c0 = 0.f, c1 = 0.f;
#pragma unroll
        for (int wi = 0; wi < 16; wi++) {
            unsigned mw = __shfl_sync(0xffffffffu, m, wi);
            int base = wi * (32 * 33) + lane;
            while (mw) {
                int p = __ffs(mw) - 1; mw &= mw - 1;
                c0 += s_wT[base + p * 33];
                if (mw) {
                    int p2 = __ffs(mw) - 1; mw &= mw - 1;
                    c1 += s_wT[base + p2 * 33];
                }
            }
        }
        dst[tb * NOUT + lane] = c0 + c1;
    }
}

// ---------------- CUBA LI readout: sum halves + scan, 4-deep prefetch ----------------
__global__ __launch_bounds__(256) void li_kernel(float* __restrict__ out) {
    int gid = blockIdx.x * blockDim.x + threadIdx.x;  // 0..4095
    const float* pA = g_cop;
    const float* pB = g_cop + (size_t)MM * NOUT;
    float v = 0.f, cur = 0.f;
    float a[4], bv[4], an[4], bn[4];
#pragma unroll
    for (int j = 0; j < 4; j++) {
        a[j]  = pA[(size_t)j * 4096 + gid];
        bv[j] = pB[(size_t)j * 4096 + gid];
    }
    for (int t0 = 0; t0 < TT; t0 += 4) {
        if (t0 + 4 < TT) {
#pragma unroll
            for (int j = 0; j < 4; j++) {
                an[j] = pA[(size_t)(t0 + 4 + j) * 4096 + gid];
                bn[j] = pB[(size_t)(t0 + 4 + j) * 4096 + gid];
            }
        }
#pragma unroll
        for (int j = 0; j < 4; j++) {
            float c = a[j] + bv[j];
            cur = cur * 0.875f + c;
            v = v + 0.125f * (cur - v);
            out[(size_t)(t0 + j) * 4096 + gid] = v;
        }
#pragma unroll
        for (int j = 0; j < 4; j++) { a[j] = an[j]; bv[j] = bn[j]; }
    }
}

// ---------------- launch ----------------
extern "C" void kernel_launch(void* const* d_in, const int* in_sizes, int n_in,
                              void* d_out, int out_size) {
    const float* spikes = (const float*)d_in[0];   // [512,128,256]
    const float* w_h    = (const float*)d_in[1];   // [1024,256]
    const float* w_o    = (const float*)d_in[2];   // [32,1024]
    float* out = (float*)d_out;                    // [512,128,32]

    cudaFuncSetAttribute(lif_kernel,  cudaFuncAttributeMaxDynamicSharedMemorySize, LIF_SMEM);
    cudaFuncSetAttribute(cout_kernel, cudaFuncAttributeMaxDynamicSharedMemorySize, COUT_SMEM);

    transpose_wh_kernel<<<(NH * NIN + 1023) / 1024, 1024>>>(w_h);
    compact_kernel<<<1024, 256>>>(spikes);
    lif_kernel<<<dim3(NH / 128, BB / 8), 512, LIF_SMEM>>>();
    cout_kernel<<<256, 512, COUT_SMEM>>>(w_o);
    li_kernel<<<16, 256>>>(out);
}